// round 1
// baseline (speedup 1.0000x reference)
#include <cuda_runtime.h>
#include <cuda_bf16.h>

#define BATCH 4
#define SEQ   2048
#define DIM   1024

// Scratch (allocation-free rule: __device__ globals)
__device__ float g_Q[BATCH * SEQ * DIM];
__device__ float g_K[BATCH * SEQ * DIM];
__device__ float g_V[BATCH * SEQ * DIM];
__device__ float g_ctx[BATCH * SEQ * DIM];
__device__ float g_scores[(long)BATCH * SEQ * SEQ];

#define BM 64
#define BN 64
#define BK 16

// C[m][n] = sum_k A[m][k] * (TRANSB ? B[n][k] : B[k][n])  (+ bias[n])
// Batched via blockIdx.z with element strides sA, sB, sC.
template<bool TRANSB, bool BIAS>
__global__ void gemm_k(const float* __restrict__ A, const float* __restrict__ B,
                       const float* __restrict__ bias, float* __restrict__ C,
                       int M, int N, int K,
                       long sA, long sB, long sC)
{
    __shared__ float As[BK][BM];
    __shared__ float Bs[BK][BN + 4];

    A += (long)blockIdx.z * sA;
    B += (long)blockIdx.z * sB;
    C += (long)blockIdx.z * sC;

    const int m0 = blockIdx.y * BM;
    const int n0 = blockIdx.x * BN;
    const int t  = threadIdx.x;          // 0..255
    const int tx = t & 15;               // 16
    const int ty = t >> 4;               // 16

    float acc[4][4] = {};

    for (int k0 = 0; k0 < K; k0 += BK) {
        // Load A tile: 64 rows x 16 k  (1024 elems, 4 per thread)
        #pragma unroll
        for (int i = 0; i < 4; i++) {
            int idx = t + i * 256;
            int mm = idx >> 4;
            int kk = idx & 15;
            As[kk][mm] = A[(long)(m0 + mm) * K + (k0 + kk)];
        }
        // Load B tile
        #pragma unroll
        for (int i = 0; i < 4; i++) {
            int idx = t + i * 256;
            if (TRANSB) {
                int nn = idx >> 4;
                int kk = idx & 15;
                Bs[kk][nn] = B[(long)(n0 + nn) * K + (k0 + kk)];
            } else {
                int kk = idx >> 6;
                int nn = idx & 63;
                Bs[kk][nn] = B[(long)(k0 + kk) * N + (n0 + nn)];
            }
        }
        __syncthreads();

        #pragma unroll
        for (int kk = 0; kk < BK; kk++) {
            float a[4], b[4];
            #pragma unroll
            for (int i = 0; i < 4; i++) a[i] = As[kk][ty * 4 + i];
            #pragma unroll
            for (int j = 0; j < 4; j++) b[j] = Bs[kk][tx * 4 + j];
            #pragma unroll
            for (int i = 0; i < 4; i++)
                #pragma unroll
                for (int j = 0; j < 4; j++)
                    acc[i][j] += a[i] * b[j];
        }
        __syncthreads();
    }

    #pragma unroll
    for (int i = 0; i < 4; i++) {
        int m = m0 + ty * 4 + i;
        #pragma unroll
        for (int j = 0; j < 4; j++) {
            int n = n0 + tx * 4 + j;
            float v = acc[i][j];
            if (BIAS) v += bias[n];
            C[(long)m * N + n] = v;
        }
    }
}

// One block per attention row (b*SEQ + q). Applies scale, mask-fill (1e-20),
// then softmax in-place over the SEQ=2048 key dimension.
__global__ void softmax_mask_k(float* __restrict__ scores,
                               const int* __restrict__ mask,
                               float scale)
{
    const long row = blockIdx.x;
    float* s = scores + row * (long)SEQ;
    const int* m = mask + row * (long)SEQ;
    const int t = threadIdx.x;  // 256 threads, 8 elems each

    float v[8];
    float mx = -1e30f;
    #pragma unroll
    for (int i = 0; i < 8; i++) {
        int k = t + i * 256;
        float x = m[k] ? 1e-20f : s[k] * scale;
        v[i] = x;
        mx = fmaxf(mx, x);
    }

    __shared__ float red[256];
    red[t] = mx;
    __syncthreads();
    #pragma unroll
    for (int off = 128; off > 0; off >>= 1) {
        if (t < off) red[t] = fmaxf(red[t], red[t + off]);
        __syncthreads();
    }
    mx = red[0];
    __syncthreads();

    float sum = 0.f;
    #pragma unroll
    for (int i = 0; i < 8; i++) {
        v[i] = expf(v[i] - mx);
        sum += v[i];
    }
    red[t] = sum;
    __syncthreads();
    #pragma unroll
    for (int off = 128; off > 0; off >>= 1) {
        if (t < off) red[t] += red[t + off];
        __syncthreads();
    }
    const float inv = 1.0f / red[0];

    #pragma unroll
    for (int i = 0; i < 8; i++) {
        int k = t + i * 256;
        s[k] = v[i] * inv;
    }
}

extern "C" void kernel_launch(void* const* d_in, const int* in_sizes, int n_in,
                              void* d_out, int out_size)
{
    const float* X    = (const float*)d_in[0];
    const int*   mask = (const int*)  d_in[1];
    const float* Wq   = (const float*)d_in[2];
    const float* bq   = (const float*)d_in[3];
    const float* Wk   = (const float*)d_in[4];
    const float* bk   = (const float*)d_in[5];
    const float* Wv   = (const float*)d_in[6];
    const float* bv   = (const float*)d_in[7];
    const float* Wo   = (const float*)d_in[8];
    const float* bo   = (const float*)d_in[9];
    float* out = (float*)d_out;

    float *Q, *K, *V, *CTX, *SC;
    cudaGetSymbolAddress((void**)&Q,   g_Q);
    cudaGetSymbolAddress((void**)&K,   g_K);
    cudaGetSymbolAddress((void**)&V,   g_V);
    cudaGetSymbolAddress((void**)&CTX, g_ctx);
    cudaGetSymbolAddress((void**)&SC,  g_scores);

    const int MS = BATCH * SEQ;  // 8192

    // 1) Q, K, V projections: [8192,1024] @ [1024,1024] + bias
    {
        dim3 grid(DIM / BN, MS / BM, 1);
        gemm_k<false, true><<<grid, 256>>>(X, Wq, bq, Q, MS, DIM, DIM, 0, 0, 0);
        gemm_k<false, true><<<grid, 256>>>(X, Wk, bk, K, MS, DIM, DIM, 0, 0, 0);
        gemm_k<false, true><<<grid, 256>>>(X, Wv, bv, V, MS, DIM, DIM, 0, 0, 0);
    }

    // 2) scores[b] = Q[b] @ K[b]^T   (batched NT)
    {
        dim3 grid(SEQ / BN, SEQ / BM, BATCH);
        gemm_k<true, false><<<grid, 256>>>(Q, K, nullptr, SC, SEQ, SEQ, DIM,
                                           (long)SEQ * DIM, (long)SEQ * DIM,
                                           (long)SEQ * SEQ);
    }

    // 3) scale + mask(1e-20) + softmax, in-place
    {
        const float scale = 1.0f / 32.0f;  // 1/sqrt(1024)
        softmax_mask_k<<<BATCH * SEQ, 256>>>(SC, mask, scale);
    }

    // 4) ctx[b] = attn[b] @ V[b]   (batched NN)
    {
        dim3 grid(DIM / BN, SEQ / BM, BATCH);
        gemm_k<false, false><<<grid, 256>>>(SC, V, nullptr, CTX, SEQ, DIM, SEQ,
                                            (long)SEQ * SEQ, (long)SEQ * DIM,
                                            (long)SEQ * DIM);
    }

    // 5) out = ctx @ Wo + bo
    {
        dim3 grid(DIM / BN, MS / BM, 1);
        gemm_k<false, true><<<grid, 256>>>(CTX, Wo, bo, out, MS, DIM, DIM, 0, 0, 0);
    }
}

// round 3
// speedup vs baseline: 4.0527x; 4.0527x over previous
#include <cuda_runtime.h>
#include <cuda_bf16.h>
#include <cstdint>

#define BATCH 4
#define SEQ   2048
#define DIM   1024
typedef __nv_bfloat16 bf16;

// ------------------------- scratch (__device__ globals) -------------------------
#define MS (BATCH * SEQ)            // 8192
__device__ bf16  g_Xhi[MS * DIM],  g_Xlo[MS * DIM];
__device__ bf16  g_Qhi[MS * DIM],  g_Qlo[MS * DIM];
__device__ bf16  g_Khi[MS * DIM],  g_Klo[MS * DIM];
__device__ float g_V  [MS * DIM];
__device__ bf16  g_VThi[MS * DIM], g_VTlo[MS * DIM];          // per-batch [DIM x SEQ]
__device__ bf16  g_WqThi[DIM*DIM], g_WqTlo[DIM*DIM];
__device__ bf16  g_WkThi[DIM*DIM], g_WkTlo[DIM*DIM];
__device__ bf16  g_WvThi[DIM*DIM], g_WvTlo[DIM*DIM];
__device__ bf16  g_WoThi[DIM*DIM], g_WoTlo[DIM*DIM];
__device__ float g_scores[(long)BATCH * SEQ * SEQ];
__device__ bf16  g_Ahi[(long)BATCH * SEQ * SEQ], g_Alo[(long)BATCH * SEQ * SEQ];
__device__ bf16  g_Chi[MS * DIM],  g_Clo[MS * DIM];           // ctx split

// ------------------------- PTX helpers -------------------------
__device__ __forceinline__ uint32_t s2u(const void* p) {
    uint32_t a;
    asm("{ .reg .u64 t; cvta.to.shared.u64 t, %1; cvt.u32.u64 %0, t; }" : "=r"(a) : "l"(p));
    return a;
}
#define CP16(dst, src) asm volatile("cp.async.cg.shared.global [%0], [%1], 16;" :: "r"(dst), "l"(src))
#define CP_COMMIT()    asm volatile("cp.async.commit_group;" ::: "memory")
template<int N> __device__ __forceinline__ void cp_wait() {
    asm volatile("cp.async.wait_group %0;" :: "n"(N) : "memory");
}
#define LDSM4(r0, r1, r2, r3, a) \
    asm volatile("ldmatrix.sync.aligned.m8n8.x4.shared.b16 {%0,%1,%2,%3}, [%4];" \
        : "=r"(r0), "=r"(r1), "=r"(r2), "=r"(r3) : "r"(a))
#define MMA16816(c, a, b0, b1) \
    asm volatile("mma.sync.aligned.m16n8k16.row.col.f32.bf16.bf16.f32 " \
        "{%0,%1,%2,%3}, {%4,%5,%6,%7}, {%8,%9}, {%0,%1,%2,%3};" \
        : "+f"((c)[0]), "+f"((c)[1]), "+f"((c)[2]), "+f"((c)[3]) \
        : "r"((a)[0]), "r"((a)[1]), "r"((a)[2]), "r"((a)[3]), "r"(b0), "r"(b1))

// ------------------------- bf16-split HMMA GEMM -------------------------
// D[m][n] = sum_k A[m][k]*B[n][k] (+bias[n]); A,B given as hi/lo bf16 splits,
// both K-major. 128x128 tile, BK=64, 3-stage cp.async pipeline, SW128 swizzle.
#define STG_BYTES 65536                 // Ahi|Alo|Bhi|Blo, 16KB each
#define SMEM_SZ   (3 * STG_BYTES + 1024)

template<bool BIAS, bool SPLITOUT>
__global__ void __launch_bounds__(256, 1)
gemm_mma(const bf16* __restrict__ Ah, const bf16* __restrict__ Al,
         const bf16* __restrict__ Bh, const bf16* __restrict__ Bl,
         const float* __restrict__ bias,
         float* Cf, bf16* Chi, bf16* Clo,
         int M, int N, int K, long sA, long sB, long sC)
{
    extern __shared__ char smem[];
    const uint32_t sb = (s2u(smem) + 1023u) & ~1023u;
    const int t = threadIdx.x, wid = t >> 5, lane = t & 31;
    const int wm = wid & 3, wn = wid >> 2;           // warp grid 4(m) x 2(n)
    const long z = blockIdx.z;
    Ah += z * sA; Al += z * sA; Bh += z * sB; Bl += z * sB;
    if (SPLITOUT) { Chi += z * sC; Clo += z * sC; } else { Cf += z * sC; }
    const int m0 = blockIdx.y * 128, n0 = blockIdx.x * 128;

    const int nch = K >> 6;                          // K / 64

    auto load_chunk = [&](int c) {
        const int k0 = c << 6;
        const uint32_t stg = sb + (uint32_t)(c % 3) * STG_BYTES;
        #pragma unroll
        for (int j = 0; j < 4; j++) {
            int si  = t + j * 256;                   // 0..1023
            int row = si >> 3;                       // 0..127
            int c16 = si & 7;                        // 16B seg in 128B row
            uint32_t off = (uint32_t)(row * 128 + c16 * 16);
            uint32_t sw  = off ^ ((off >> 3) & 0x70);
            long ga = (long)(m0 + row) * K + k0 + c16 * 8;
            long gb = (long)(n0 + row) * K + k0 + c16 * 8;
            CP16(stg +         sw, Ah + ga);
            CP16(stg + 16384 + sw, Al + ga);
            CP16(stg + 32768 + sw, Bh + gb);
            CP16(stg + 49152 + sw, Bl + gb);
        }
    };

    for (int c = 0; c < 3 && c < nch; c++) { load_chunk(c); CP_COMMIT(); }

    float acc[2][8][4];
    #pragma unroll
    for (int i = 0; i < 2; i++)
        #pragma unroll
        for (int j = 0; j < 8; j++)
            #pragma unroll
            for (int r = 0; r < 4; r++) acc[i][j][r] = 0.f;

    // per-lane ldmatrix addressing: row = base + (lane&15), seg = 2*ks + (lane>>4)
    const int lr = lane & 15, lh = lane >> 4;
    // A frag rows (2 frags of m16), B frag rows (4 frags of n16)
    uint32_t arow[2], ax[2], brow[4], bx[4];
    #pragma unroll
    for (int i = 0; i < 2; i++) {
        int r = wm * 32 + i * 16 + lr;
        arow[i] = (uint32_t)(r * 128); ax[i] = (uint32_t)(r & 7);
    }
    #pragma unroll
    for (int j = 0; j < 4; j++) {
        int r = wn * 64 + j * 16 + lr;
        brow[j] = (uint32_t)(r * 128); bx[j] = (uint32_t)(r & 7);
    }

    for (int i = 0; i < nch; i++) {
        int rem = nch - 1 - i;
        if (rem >= 2) cp_wait<2>(); else if (rem == 1) cp_wait<1>(); else cp_wait<0>();
        __syncthreads();

        const uint32_t stg = sb + (uint32_t)(i % 3) * STG_BYTES;
        #pragma unroll
        for (int ks = 0; ks < 4; ks++) {
            const uint32_t seg = (uint32_t)(2 * ks + lh);
            uint32_t ah[2][4], al2[2][4];
            #pragma unroll
            for (int f = 0; f < 2; f++) {
                uint32_t o = arow[f] + ((seg ^ ax[f]) << 4);
                LDSM4(ah[f][0],  ah[f][1],  ah[f][2],  ah[f][3],  stg + o);
                LDSM4(al2[f][0], al2[f][1], al2[f][2], al2[f][3], stg + 16384 + o);
            }
            #pragma unroll
            for (int j = 0; j < 4; j++) {
                uint32_t o = brow[j] + ((seg ^ bx[j]) << 4);
                uint32_t bh[4], bl[4];
                LDSM4(bh[0], bh[1], bh[2], bh[3], stg + 32768 + o);
                LDSM4(bl[0], bl[1], bl[2], bl[3], stg + 49152 + o);
                #pragma unroll
                for (int f = 0; f < 2; f++) {
                    // n-frag 0 of this n16: regs {r0, r2}; n-frag 1: {r1, r3}
                    MMA16816(acc[f][2 * j],     ah[f],  bh[0], bh[2]);
                    MMA16816(acc[f][2 * j],     ah[f],  bl[0], bl[2]);
                    MMA16816(acc[f][2 * j],     al2[f], bh[0], bh[2]);
                    MMA16816(acc[f][2 * j + 1], ah[f],  bh[1], bh[3]);
                    MMA16816(acc[f][2 * j + 1], ah[f],  bl[1], bl[3]);
                    MMA16816(acc[f][2 * j + 1], al2[f], bh[1], bh[3]);
                }
            }
        }
        __syncthreads();
        if (i + 3 < nch) { load_chunk(i + 3); CP_COMMIT(); }
    }

    // epilogue: lane holds (m = l/4 [+8], n = (l%4)*2 [+1]) per frag
    const int ml = lane >> 2, nl = (lane & 3) * 2;
    #pragma unroll
    for (int f = 0; f < 2; f++) {
        #pragma unroll
        for (int j = 0; j < 8; j++) {
            const int n = n0 + wn * 64 + j * 8 + nl;
            #pragma unroll
            for (int half = 0; half < 2; half++) {
                const int m = m0 + wm * 32 + f * 16 + ml + half * 8;
                float v0 = acc[f][j][half * 2];
                float v1 = acc[f][j][half * 2 + 1];
                if (BIAS) { v0 += bias[n]; v1 += bias[n + 1]; }
                if (SPLITOUT) {
                    bf16 h0 = __float2bfloat16(v0), h1 = __float2bfloat16(v1);
                    bf16 l0 = __float2bfloat16(v0 - __bfloat162float(h0));
                    bf16 l1 = __float2bfloat16(v1 - __bfloat162float(h1));
                    __nv_bfloat162 hh; hh.x = h0; hh.y = h1;
                    __nv_bfloat162 ll; ll.x = l0; ll.y = l1;
                    *reinterpret_cast<__nv_bfloat162*>(Chi + (long)m * N + n) = hh;
                    *reinterpret_cast<__nv_bfloat162*>(Clo + (long)m * N + n) = ll;
                } else {
                    float2 vv; vv.x = v0; vv.y = v1;
                    *reinterpret_cast<float2*>(Cf + (long)m * N + n) = vv;
                }
            }
        }
    }
}

// ------------------------- conversion kernels -------------------------
__global__ void split_flat(const float* __restrict__ s, bf16* __restrict__ h,
                           bf16* __restrict__ l, long n)
{
    long i = ((long)blockIdx.x * 256 + threadIdx.x) * 4;
    if (i >= n) return;
    float4 v = *reinterpret_cast<const float4*>(s + i);
    float a[4] = {v.x, v.y, v.z, v.w};
    #pragma unroll
    for (int j = 0; j < 4; j++) {
        bf16 hh = __float2bfloat16(a[j]);
        h[i + j] = hh;
        l[i + j] = __float2bfloat16(a[j] - __bfloat162float(hh));
    }
}

// out[c][r] = src[r][c], split into hi/lo
__global__ void splitT_k(const float* __restrict__ src, bf16* __restrict__ hi,
                         bf16* __restrict__ lo, int R, int C, long inS, long outS)
{
    __shared__ float tl[32][33];
    src += blockIdx.z * inS; hi += blockIdx.z * outS; lo += blockIdx.z * outS;
    int c0 = blockIdx.x * 32, r0 = blockIdx.y * 32;
    int tx = threadIdx.x, ty = threadIdx.y;   // (32, 8)
    #pragma unroll
    for (int j = 0; j < 32; j += 8)
        tl[ty + j][tx] = src[(long)(r0 + ty + j) * C + c0 + tx];
    __syncthreads();
    #pragma unroll
    for (int j = 0; j < 32; j += 8) {
        float v = tl[tx][ty + j];
        bf16 h = __float2bfloat16(v);
        long o = (long)(c0 + ty + j) * R + r0 + tx;
        hi[o] = h;
        lo[o] = __float2bfloat16(v - __bfloat162float(h));
    }
}

// scale + mask(1e-20) + softmax over SEQ, output split bf16
__global__ void softmax_split_k(const float* __restrict__ scores,
                                const int* __restrict__ mask,
                                bf16* __restrict__ ah, bf16* __restrict__ al,
                                float scale)
{
    const long row = blockIdx.x;
    const float* s = scores + row * (long)SEQ;
    const int*   m = mask   + row * (long)SEQ;
    const int t = threadIdx.x;   // 256 threads, 8 each

    float v[8];
    float mx = -1e30f;
    #pragma unroll
    for (int i = 0; i < 8; i++) {
        int k = t + i * 256;
        float x = m[k] ? 1e-20f : s[k] * scale;
        v[i] = x;
        mx = fmaxf(mx, x);
    }
    __shared__ float red[256];
    red[t] = mx; __syncthreads();
    #pragma unroll
    for (int off = 128; off > 0; off >>= 1) {
        if (t < off) red[t] = fmaxf(red[t], red[t + off]);
        __syncthreads();
    }
    mx = red[0]; __syncthreads();

    float sum = 0.f;
    #pragma unroll
    for (int i = 0; i < 8; i++) { v[i] = expf(v[i] - mx); sum += v[i]; }
    red[t] = sum; __syncthreads();
    #pragma unroll
    for (int off = 128; off > 0; off >>= 1) {
        if (t < off) red[t] += red[t + off];
        __syncthreads();
    }
    const float inv = 1.0f / red[0];

    #pragma unroll
    for (int i = 0; i < 8; i++) {
        int k = t + i * 256;
        float a = v[i] * inv;
        bf16 h = __float2bfloat16(a);
        ah[row * (long)SEQ + k] = h;
        al[row * (long)SEQ + k] = __float2bfloat16(a - __bfloat162float(h));
    }
}

// ------------------------- launch -------------------------
extern "C" void kernel_launch(void* const* d_in, const int* in_sizes, int n_in,
                              void* d_out, int out_size)
{
    const float* X    = (const float*)d_in[0];
    const int*   mask = (const int*)  d_in[1];
    const float* Wq   = (const float*)d_in[2];
    const float* bq   = (const float*)d_in[3];
    const float* Wk   = (const float*)d_in[4];
    const float* bk   = (const float*)d_in[5];
    const float* Wv   = (const float*)d_in[6];
    const float* bv   = (const float*)d_in[7];
    const float* Wo   = (const float*)d_in[8];
    const float* bo   = (const float*)d_in[9];
    float* out = (float*)d_out;

    bf16 *Xhi, *Xlo, *Qhi, *Qlo, *Khi, *Klo, *VThi, *VTlo;
    bf16 *WqThi, *WqTlo, *WkThi, *WkTlo, *WvThi, *WvTlo, *WoThi, *WoTlo;
    bf16 *Ahi, *Alo, *Chi, *Clo;
    float *V, *SC;
    cudaGetSymbolAddress((void**)&Xhi, g_Xhi);   cudaGetSymbolAddress((void**)&Xlo, g_Xlo);
    cudaGetSymbolAddress((void**)&Qhi, g_Qhi);   cudaGetSymbolAddress((void**)&Qlo, g_Qlo);
    cudaGetSymbolAddress((void**)&Khi, g_Khi);   cudaGetSymbolAddress((void**)&Klo, g_Klo);
    cudaGetSymbolAddress((void**)&V,   g_V);
    cudaGetSymbolAddress((void**)&VThi, g_VThi); cudaGetSymbolAddress((void**)&VTlo, g_VTlo);
    cudaGetSymbolAddress((void**)&WqThi, g_WqThi); cudaGetSymbolAddress((void**)&WqTlo, g_WqTlo);
    cudaGetSymbolAddress((void**)&WkThi, g_WkThi); cudaGetSymbolAddress((void**)&WkTlo, g_WkTlo);
    cudaGetSymbolAddress((void**)&WvThi, g_WvThi); cudaGetSymbolAddress((void**)&WvTlo, g_WvTlo);
    cudaGetSymbolAddress((void**)&WoThi, g_WoThi); cudaGetSymbolAddress((void**)&WoTlo, g_WoTlo);
    cudaGetSymbolAddress((void**)&SC,  g_scores);
    cudaGetSymbolAddress((void**)&Ahi, g_Ahi);   cudaGetSymbolAddress((void**)&Alo, g_Alo);
    cudaGetSymbolAddress((void**)&Chi, g_Chi);   cudaGetSymbolAddress((void**)&Clo, g_Clo);

    cudaFuncSetAttribute(gemm_mma<true,  true >, cudaFuncAttributeMaxDynamicSharedMemorySize, SMEM_SZ);
    cudaFuncSetAttribute(gemm_mma<true,  false>, cudaFuncAttributeMaxDynamicSharedMemorySize, SMEM_SZ);
    cudaFuncSetAttribute(gemm_mma<false, false>, cudaFuncAttributeMaxDynamicSharedMemorySize, SMEM_SZ);
    cudaFuncSetAttribute(gemm_mma<false, true >, cudaFuncAttributeMaxDynamicSharedMemorySize, SMEM_SZ);

    // 0) input conversions
    split_flat<<<(MS * DIM) / 1024, 256>>>(X, Xhi, Xlo, (long)MS * DIM);
    {
        dim3 g(DIM / 32, DIM / 32, 1); dim3 b(32, 8);
        splitT_k<<<g, b>>>(Wq, WqThi, WqTlo, DIM, DIM, 0, 0);
        splitT_k<<<g, b>>>(Wk, WkThi, WkTlo, DIM, DIM, 0, 0);
        splitT_k<<<g, b>>>(Wv, WvThi, WvTlo, DIM, DIM, 0, 0);
        splitT_k<<<g, b>>>(Wo, WoThi, WoTlo, DIM, DIM, 0, 0);
    }

    // 1) projections: [8192x1024] @ W^T-layout  (Q,K split-out; V fp32)
    {
        dim3 g(DIM / 128, MS / 128, 1);
        gemm_mma<true, true ><<<g, 256, SMEM_SZ>>>(Xhi, Xlo, WqThi, WqTlo, bq,
                                                   nullptr, Qhi, Qlo, MS, DIM, DIM, 0, 0, 0);
        gemm_mma<true, true ><<<g, 256, SMEM_SZ>>>(Xhi, Xlo, WkThi, WkTlo, bk,
                                                   nullptr, Khi, Klo, MS, DIM, DIM, 0, 0, 0);
        gemm_mma<true, false><<<g, 256, SMEM_SZ>>>(Xhi, Xlo, WvThi, WvTlo, bv,
                                                   V, nullptr, nullptr, MS, DIM, DIM, 0, 0, 0);
    }

    // 2) V transpose+split per batch: [2048x1024] -> [1024x2048]
    {
        dim3 g(DIM / 32, SEQ / 32, BATCH); dim3 b(32, 8);
        splitT_k<<<g, b>>>(V, VThi, VTlo, SEQ, DIM, (long)SEQ * DIM, (long)SEQ * DIM);
    }

    // 3) scores[b] = Q[b] @ K[b]^T
    {
        dim3 g(SEQ / 128, SEQ / 128, BATCH);
        gemm_mma<false, false><<<g, 256, SMEM_SZ>>>(Qhi, Qlo, Khi, Klo, nullptr,
                                                    SC, nullptr, nullptr, SEQ, SEQ, DIM,
                                                    (long)SEQ * DIM, (long)SEQ * DIM, (long)SEQ * SEQ);
    }

    // 4) scale + mask + softmax -> split bf16 attn
    softmax_split_k<<<BATCH * SEQ, 256>>>(SC, mask, Ahi, Alo, 1.0f / 32.0f);

    // 5) ctx[b] = attn[b] @ V[b]  (B = V^T, K-major)
    {
        dim3 g(DIM / 128, SEQ / 128, BATCH);
        gemm_mma<false, true><<<g, 256, SMEM_SZ>>>(Ahi, Alo, VThi, VTlo, nullptr,
                                                   nullptr, Chi, Clo, SEQ, DIM, SEQ,
                                                   (long)SEQ * SEQ, (long)DIM * SEQ, (long)SEQ * DIM);
    }

    // 6) out = ctx @ Wo + bo
    {
        dim3 g(DIM / 128, MS / 128, 1);
        gemm_mma<true, false><<<g, 256, SMEM_SZ>>>(Chi, Clo, WoThi, WoTlo, bo,
                                                   out, nullptr, nullptr, MS, DIM, DIM, 0, 0, 0);
    }
}